// round 4
// baseline (speedup 1.0000x reference)
#include <cuda_runtime.h>
#include <cuda_bf16.h>
#include <math.h>

#define N_NODES 100000
#define E_EDGES 1600000
#define IN_F 20
#define H_F 64
#define NHEADS 4
#define HO_F 32
#define EPS_BN 1e-5f
#define SCAN_B 512
#define NB_SCAN ((N_NODES + SCAN_B - 1) / SCAN_B)   // 196
#define CAP 64                                      // smem exp-cache depth per node

// ---------------- scratch (device globals; no allocation) ----------------
__device__ int   d_cnt[N_NODES];                    // self-resetting (zero after scan1)
__device__ int   d_rowptr[N_NODES + 1];
__device__ int   d_cursor[N_NODES];
__device__ int   d_bsum[NB_SCAN];
__device__ int   d_csr_src[E_EDGES];
__device__ float d_aggrx[N_NODES * IN_F];
__device__ float d_h1[N_NODES * H_F];
__device__ __nv_bfloat16 d_hgb[N_NODES * NHEADS * H_F];  // 51.2 MB (L2-resident)
__device__ float d_asrc[N_NODES * NHEADS];
__device__ float d_adst[N_NODES * NHEADS];
__device__ float d_h2[N_NODES * H_F];
__device__ float d_aggr2[N_NODES * H_F];

// ---------------- f32x2 helpers (sm_103 FFMA2) ----------------
__device__ __forceinline__ unsigned long long pk2(float a, float b) {
    unsigned long long r;
    asm("mov.b64 %0, {%1,%2};" : "=l"(r) : "f"(a), "f"(b));
    return r;
}
__device__ __forceinline__ unsigned long long fma2(unsigned long long a,
                                                   unsigned long long b,
                                                   unsigned long long c) {
    unsigned long long d;
    asm("fma.rn.f32x2 %0, %1, %2, %3;" : "=l"(d) : "l"(a), "l"(b), "l"(c));
    return d;
}
__device__ __forceinline__ float2 upk2(unsigned long long v) {
    float2 f;
    asm("mov.b64 {%0,%1}, %2;" : "=f"(f.x), "=f"(f.y) : "l"(v));
    return f;
}

// ---------------- CSR build ----------------
__global__ void k_count(const int* __restrict__ ei) {
    int e = blockIdx.x * blockDim.x + threadIdx.x;
    if (e >= E_EDGES) return;
    atomicAdd(&d_cnt[ei[E_EDGES + e]], 1);
}
__global__ void k_scan1() {
    __shared__ int sd[SCAN_B];
    int tid = threadIdx.x;
    int i = blockIdx.x * SCAN_B + tid;
    int v = (i < N_NODES) ? d_cnt[i] : 0;
    if (i < N_NODES) d_cnt[i] = 0;                   // self-reset for next replay
    sd[tid] = v;
    __syncthreads();
    for (int o = 1; o < SCAN_B; o <<= 1) {
        int t = (tid >= o) ? sd[tid - o] : 0;
        __syncthreads();
        sd[tid] += t;
        __syncthreads();
    }
    if (i < N_NODES) d_rowptr[i] = sd[tid] - v;      // exclusive within block
    if (tid == SCAN_B - 1) d_bsum[blockIdx.x] = sd[tid];
}
// merged scan of block sums + apply: each block redundantly scans the 196 sums
__global__ void k_scan23() {
    __shared__ int sd[256];
    int tid = threadIdx.x;
    int bv = (tid < NB_SCAN) ? d_bsum[tid] : 0;
    sd[tid] = bv;
    __syncthreads();
    for (int o = 1; o < 256; o <<= 1) {
        int t = (tid >= o) ? sd[tid - o] : 0;
        __syncthreads();
        sd[tid] += t;
        __syncthreads();
    }
    int off = (blockIdx.x == 0) ? 0 : sd[blockIdx.x - 1];
    // apply to this block's chunk (SCAN_B elements, 512 = 2x256 threads)
    for (int k = 0; k < SCAN_B; k += 256) {
        int i = blockIdx.x * SCAN_B + k + tid;
        if (i < N_NODES) {
            int r = d_rowptr[i] + off;
            d_rowptr[i] = r;
            d_cursor[i] = r;
        }
    }
    if (blockIdx.x == 0 && tid == 0) d_rowptr[N_NODES] = E_EDGES;
}
__global__ void k_scatter(const int* __restrict__ ei) {
    int e = blockIdx.x * blockDim.x + threadIdx.x;
    if (e >= E_EDGES) return;
    int s = ei[e], d = ei[E_EDGES + e];
    int pos = atomicAdd(&d_cursor[d], 1);
    d_csr_src[pos] = s;
}

// ---------------- SAGE1 mean aggregation (CSR, warp per node, prefetched) ------
__global__ __launch_bounds__(256) void k_sage1_csr(const float* __restrict__ x) {
    int n = blockIdx.x * 8 + (threadIdx.x >> 5);
    int lane = threadIdx.x & 31;
    if (n >= N_NODES) return;
    int row = d_rowptr[n];
    int deg = d_rowptr[n + 1] - row;
    float acc = 0.0f;
    bool fl = lane < IN_F;
    for (int c = 0; c < deg; c += 32) {
        int idx = c + lane;
        int s_l = (idx < deg) ? __ldg(&d_csr_src[row + idx]) : 0;
        int kmax = min(32, deg - c);
        int s0 = __shfl_sync(0xffffffffu, s_l, 0);
        float v_cur = fl ? __ldg(&x[(size_t)s0 * IN_F + lane]) : 0.0f;
        for (int i = 0; i < kmax; i++) {
            float v_next = 0.0f;
            if (i + 1 < kmax) {
                int sn = __shfl_sync(0xffffffffu, s_l, i + 1);
                if (fl) v_next = __ldg(&x[(size_t)sn * IN_F + lane]);
            }
            acc += v_cur;
            v_cur = v_next;
        }
    }
    float inv = 1.0f / fmaxf((float)deg, 1.0f);
    if (fl) d_aggrx[(size_t)n * IN_F + lane] = acc * inv;
}

// ---------------- SAGE1 GEMM + BN + ReLU ----------------
__global__ void k_sage1_gemm(const float* __restrict__ x,
                             const float* __restrict__ Wl, const float* __restrict__ Wr,
                             const float* __restrict__ b,
                             const float* __restrict__ g, const float* __restrict__ be,
                             const float* __restrict__ m, const float* __restrict__ v) {
    __shared__ float sWl[IN_F * H_F], sWr[IN_F * H_F];
    for (int i = threadIdx.x; i < IN_F * H_F; i += blockDim.x) { sWl[i] = Wl[i]; sWr[i] = Wr[i]; }
    __syncthreads();
    int t = blockIdx.x * blockDim.x + threadIdx.x;
    if (t >= N_NODES * H_F) return;
    int n = t >> 6, j = t & 63;
    const float* ax = d_aggrx + (size_t)n * IN_F;
    const float* xr = x + (size_t)n * IN_F;
    float acc = b[j];
#pragma unroll
    for (int k = 0; k < IN_F; k++) {
        acc = fmaf(ax[k], sWl[k * H_F + j], acc);
        acc = fmaf(xr[k], sWr[k * H_F + j], acc);
    }
    float sc = g[j] * rsqrtf(v[j] + EPS_BN);
    float y = (acc - m[j]) * sc + be[j];
    d_h1[t] = fmaxf(y, 0.0f);
}

// ---------------- GAT feature GEMM (f32x2 FFMA2, bf16 out) + att logits ----
__global__ __launch_bounds__(256) void k_gat_gemm(const float* __restrict__ Wg,
                                                  const float* __restrict__ att_src,
                                                  const float* __restrict__ att_dst) {
    __shared__ float sh[32][64];
    int tid = threadIdx.x;
    int g = tid >> 6, j = tid & 63;
    int nbase = blockIdx.x * 32;
    {
        const float4* src = (const float4*)(d_h1 + (size_t)nbase * H_F);
        float4* dst4 = (float4*)&sh[0][0];
        dst4[tid] = src[tid];
        dst4[tid + 256] = src[tid + 256];
    }
    __syncthreads();

    const float4* W4 = (const float4*)Wg;
    unsigned long long alo[8], ahi[8];
#pragma unroll
    for (int i = 0; i < 8; i++) { alo[i] = 0ull; ahi[i] = 0ull; }

    const float4* sh4 = (const float4*)&sh[0][0];
    int nrow = g * 8;
#pragma unroll
    for (int k4 = 0; k4 < 16; k4++) {
        float4 w0 = __ldg(&W4[(k4 * 4 + 0) * 64 + j]);
        float4 w1 = __ldg(&W4[(k4 * 4 + 1) * 64 + j]);
        float4 w2 = __ldg(&W4[(k4 * 4 + 2) * 64 + j]);
        float4 w3 = __ldg(&W4[(k4 * 4 + 3) * 64 + j]);
        unsigned long long w0l = pk2(w0.x, w0.y), w0h = pk2(w0.z, w0.w);
        unsigned long long w1l = pk2(w1.x, w1.y), w1h = pk2(w1.z, w1.w);
        unsigned long long w2l = pk2(w2.x, w2.y), w2h = pk2(w2.z, w2.w);
        unsigned long long w3l = pk2(w3.x, w3.y), w3h = pk2(w3.z, w3.w);
#pragma unroll
        for (int i = 0; i < 8; i++) {
            float4 h = sh4[(nrow + i) * 16 + k4];
            unsigned long long hx = pk2(h.x, h.x);
            alo[i] = fma2(hx, w0l, alo[i]); ahi[i] = fma2(hx, w0h, ahi[i]);
            unsigned long long hy = pk2(h.y, h.y);
            alo[i] = fma2(hy, w1l, alo[i]); ahi[i] = fma2(hy, w1h, ahi[i]);
            unsigned long long hz = pk2(h.z, h.z);
            alo[i] = fma2(hz, w2l, alo[i]); ahi[i] = fma2(hz, w2h, ahi[i]);
            unsigned long long hw = pk2(h.w, h.w);
            alo[i] = fma2(hw, w3l, alo[i]); ahi[i] = fma2(hw, w3h, ahi[i]);
        }
    }

    // attention weight slices
    int head = j >> 4;
    int db = 4 * (j & 15);
    float was0 = __ldg(&att_src[head * 64 + db + 0]);
    float was1 = __ldg(&att_src[head * 64 + db + 1]);
    float was2 = __ldg(&att_src[head * 64 + db + 2]);
    float was3 = __ldg(&att_src[head * 64 + db + 3]);
    float wad0 = __ldg(&att_dst[head * 64 + db + 0]);
    float wad1 = __ldg(&att_dst[head * 64 + db + 1]);
    float wad2 = __ldg(&att_dst[head * 64 + db + 2]);
    float wad3 = __ldg(&att_dst[head * 64 + db + 3]);

#pragma unroll
    for (int i = 0; i < 8; i++) {
        float2 a01 = upk2(alo[i]);
        float2 a23 = upk2(ahi[i]);
        int n = nbase + nrow + i;
        // bf16 store
        __nv_bfloat162 p0 = __float22bfloat162_rn(a01);
        __nv_bfloat162 p1 = __float22bfloat162_rn(a23);
        uint2 u;
        u.x = *reinterpret_cast<unsigned int*>(&p0);
        u.y = *reinterpret_cast<unsigned int*>(&p1);
        *reinterpret_cast<uint2*>(d_hgb + (size_t)n * 256 + j * 4) = u;
        // logits
        float ps = a01.x * was0 + a01.y * was1 + a23.x * was2 + a23.y * was3;
        float pd = a01.x * wad0 + a01.y * wad1 + a23.x * wad2 + a23.y * wad3;
#pragma unroll
        for (int o = 8; o; o >>= 1) {
            ps += __shfl_down_sync(0xffffffffu, ps, o, 16);
            pd += __shfl_down_sync(0xffffffffu, pd, o, 16);
        }
        if ((j & 15) == 0) {
            d_asrc[n * NHEADS + head] = ps;
            d_adst[n * NHEADS + head] = pd;
        }
    }
}

// ---------------- GAT CSR aggregation + fused epilogue (warp per node) ---------
__global__ __launch_bounds__(256) void k_gat_csr(const float* __restrict__ bg,
                                                 const float* __restrict__ g2,
                                                 const float* __restrict__ be2,
                                                 const float* __restrict__ m2,
                                                 const float* __restrict__ v2) {
    __shared__ float sExp[8][CAP * 4];
    int w = threadIdx.x >> 5;
    int lane = threadIdx.x & 31;
    int n = blockIdx.x * 8 + w;
    if (n >= N_NODES) return;
    int row = d_rowptr[n];
    int deg = d_rowptr[n + 1] - row;

    float4 ad = *(const float4*)&d_adst[n * 4];

    // phase 1: denominators + exp cache
    float4 den = make_float4(0.f, 0.f, 0.f, 0.f);
    for (int c = 0; c < deg; c += 32) {
        int idx = c + lane;
        bool val = idx < deg;
        int s = val ? __ldg(&d_csr_src[row + idx]) : 0;
        float4 a = *(const float4*)&d_asrc[s * 4];
        float4 ex;
        float t;
        t = a.x + ad.x; t = t > 0.f ? t : 0.2f * t; ex.x = __expf(t);
        t = a.y + ad.y; t = t > 0.f ? t : 0.2f * t; ex.y = __expf(t);
        t = a.z + ad.z; t = t > 0.f ? t : 0.2f * t; ex.z = __expf(t);
        t = a.w + ad.w; t = t > 0.f ? t : 0.2f * t; ex.w = __expf(t);
        if (val) {
            den.x += ex.x; den.y += ex.y; den.z += ex.z; den.w += ex.w;
            if (idx < CAP) *(float4*)&sExp[w][idx * 4] = ex;
        }
    }
#pragma unroll
    for (int o = 16; o; o >>= 1) {
        den.x += __shfl_xor_sync(0xffffffffu, den.x, o);
        den.y += __shfl_xor_sync(0xffffffffu, den.y, o);
        den.z += __shfl_xor_sync(0xffffffffu, den.z, o);
        den.w += __shfl_xor_sync(0xffffffffu, den.w, o);
    }

    int head = lane >> 3;
    float denH = head == 0 ? den.x : head == 1 ? den.y : head == 2 ? den.z : den.w;
    float adH  = head == 0 ? ad.x  : head == 1 ? ad.y  : head == 2 ? ad.z  : ad.w;
    float invd = 1.0f / (denH + 1e-16f);

    // phase 2: prefetched alpha-weighted aggregation
    float acc[8];
#pragma unroll
    for (int q = 0; q < 8; q++) acc[q] = 0.0f;
    const uint4* hg4 = (const uint4*)d_hgb;   // row = 32 uint4
    for (int c = 0; c < deg; c += 32) {
        int idx = c + lane;
        int s_l = (idx < deg) ? __ldg(&d_csr_src[row + idx]) : 0;
        int kmax = min(32, deg - c);
        int s0 = __shfl_sync(0xffffffffu, s_l, 0);
        uint4 v_cur = __ldg(&hg4[(size_t)s0 * 32 + lane]);
        int s_cur = s0;
        for (int i = 0; i < kmax; i++) {
            uint4 v_next = make_uint4(0, 0, 0, 0);
            int s_next = 0;
            if (i + 1 < kmax) {
                s_next = __shfl_sync(0xffffffffu, s_l, i + 1);
                v_next = __ldg(&hg4[(size_t)s_next * 32 + lane]);
            }
            int eidx = c + i;
            float ex;
            if (eidx < CAP) {
                ex = sExp[w][eidx * 4 + head];
            } else {
                float a = __ldg(&d_asrc[s_cur * 4 + head]) + adH;
                a = a > 0.f ? a : 0.2f * a;
                ex = __expf(a);
            }
            float alpha = ex * invd;
            const __nv_bfloat162* bp = (const __nv_bfloat162*)&v_cur;
#pragma unroll
            for (int q = 0; q < 4; q++) {
                float2 f = __bfloat1622float2(bp[q]);
                acc[q * 2 + 0] = fmaf(alpha, f.x, acc[q * 2 + 0]);
                acc[q * 2 + 1] = fmaf(alpha, f.y, acc[q * 2 + 1]);
            }
            v_cur = v_next;
            s_cur = s_next;
        }
    }
#pragma unroll
    for (int q = 0; q < 8; q++) {
        acc[q] += __shfl_xor_sync(0xffffffffu, acc[q], 8);
        acc[q] += __shfl_xor_sync(0xffffffffu, acc[q], 16);
    }
    if (lane < 8) {
#pragma unroll
        for (int q = 0; q < 8; q++) {
            int j = lane * 8 + q;
            float sc = __ldg(&g2[j]) * rsqrtf(__ldg(&v2[j]) + EPS_BN);
            float y = (acc[q] * 0.25f + __ldg(&bg[j]) - __ldg(&m2[j])) * sc + __ldg(&be2[j]);
            d_h2[(size_t)n * H_F + j] = fmaxf(y, 0.0f);
        }
    }
}

// ---------------- SAGE3 mean aggregation (CSR, warp per node, 2 edges/iter) ----
__global__ __launch_bounds__(256) void k_sage3_csr() {
    int n = blockIdx.x * 8 + (threadIdx.x >> 5);
    int lane = threadIdx.x & 31;
    if (n >= N_NODES) return;
    int row = d_rowptr[n];
    int deg = d_rowptr[n + 1] - row;
    int half = lane >> 4;
    int f = lane & 15;
    float4 acc = make_float4(0.f, 0.f, 0.f, 0.f);
    const float4* h24 = (const float4*)d_h2;   // row = 16 float4
    for (int c = 0; c < deg; c += 32) {
        int idx = c + lane;
        int s_l = (idx < deg) ? __ldg(&d_csr_src[row + idx]) : 0;
        int kmax = min(32, deg - c);
        for (int i = 0; i < kmax; i += 2) {
            int e = i + half;
            int s = __shfl_sync(0xffffffffu, s_l, e & 31);
            if (e < kmax) {
                float4 vv = __ldg(&h24[(size_t)s * 16 + f]);
                acc.x += vv.x; acc.y += vv.y; acc.z += vv.z; acc.w += vv.w;
            }
        }
    }
    acc.x += __shfl_xor_sync(0xffffffffu, acc.x, 16);
    acc.y += __shfl_xor_sync(0xffffffffu, acc.y, 16);
    acc.z += __shfl_xor_sync(0xffffffffu, acc.z, 16);
    acc.w += __shfl_xor_sync(0xffffffffu, acc.w, 16);
    if (lane < 16) {
        float inv = 1.0f / fmaxf((float)deg, 1.0f);
        acc.x *= inv; acc.y *= inv; acc.z *= inv; acc.w *= inv;
        ((float4*)d_aggr2)[(size_t)n * 16 + f] = acc;
    }
}

// ---------------- SAGE3 GEMM + BN + ReLU + skip + classifier + log_softmax -----
// warp per node: lane = output col j of h3 (HO_F = 32)
__global__ __launch_bounds__(256) void k_sage3_cls(const float* __restrict__ x,
                             const float* __restrict__ Wl, const float* __restrict__ Wr,
                             const float* __restrict__ b,
                             const float* __restrict__ g, const float* __restrict__ be,
                             const float* __restrict__ m, const float* __restrict__ v,
                             const float* __restrict__ Wskip, const float* __restrict__ bskip,
                             const float* __restrict__ Wc1, const float* __restrict__ bc1,
                             const float* __restrict__ Wc2, const float* __restrict__ bc2,
                             float* __restrict__ out) {
    __shared__ float sWl[H_F * HO_F], sWr[H_F * HO_F], sWs[IN_F * HO_F];
    __shared__ float sW1[32 * 32], sb1[32], sW2[64];
    for (int i = threadIdx.x; i < H_F * HO_F; i += blockDim.x) { sWl[i] = Wl[i]; sWr[i] = Wr[i]; }
    for (int i = threadIdx.x; i < IN_F * HO_F; i += blockDim.x) sWs[i] = Wskip[i];
    for (int i = threadIdx.x; i < 32 * 32; i += blockDim.x) sW1[i] = Wc1[i];
    if (threadIdx.x < 32) sb1[threadIdx.x] = bc1[threadIdx.x];
    else if (threadIdx.x < 96) sW2[threadIdx.x - 32] = Wc2[threadIdx.x - 32];
    __syncthreads();
    int n = blockIdx.x * 8 + (threadIdx.x >> 5);
    int j = threadIdx.x & 31;
    if (n >= N_NODES) return;
    const float* ag = d_aggr2 + (size_t)n * H_F;
    const float* hr = d_h2 + (size_t)n * H_F;
    float acc = b[j];
#pragma unroll
    for (int k = 0; k < H_F; k++) {
        acc = fmaf(ag[k], sWl[k * HO_F + j], acc);
        acc = fmaf(hr[k], sWr[k * HO_F + j], acc);
    }
    float ident = bskip[j];
    const float* xr = x + (size_t)n * IN_F;
#pragma unroll
    for (int k = 0; k < IN_F; k++) ident = fmaf(xr[k], sWs[k * HO_F + j], ident);
    float sc = g[j] * rsqrtf(v[j] + EPS_BN);
    float y = (acc - m[j]) * sc + be[j];
    float hv = fmaxf(y, 0.0f) + ident;       // h3[n][j]
    // classifier
    float s = sb1[j];
#pragma unroll
    for (int k = 0; k < 32; k++) {
        float bb = __shfl_sync(0xffffffffu, hv, k);
        s = fmaf(bb, sW1[k * 32 + j], s);
    }
    s = fmaxf(s, 0.0f);
    float p0 = s * sW2[j * 2];
    float p1 = s * sW2[j * 2 + 1];
#pragma unroll
    for (int o = 16; o; o >>= 1) {
        p0 += __shfl_down_sync(0xffffffffu, p0, o);
        p1 += __shfl_down_sync(0xffffffffu, p1, o);
    }
    if (j == 0) {
        float l0 = p0 + bc2[0], l1 = p1 + bc2[1];
        float mx = fmaxf(l0, l1);
        float lse = mx + logf(__expf(l0 - mx) + __expf(l1 - mx));
        out[(size_t)n * 2]     = l0 - lse;
        out[(size_t)n * 2 + 1] = l1 - lse;
    }
}

// ---------------- launch ----------------
extern "C" void kernel_launch(void* const* d_in, const int* in_sizes, int n_in,
                              void* d_out, int out_size) {
    const float* x       = (const float*)d_in[0];
    const int*   ei      = (const int*)d_in[1];
    const float* W1l     = (const float*)d_in[2];
    const float* W1r     = (const float*)d_in[3];
    const float* b1      = (const float*)d_in[4];
    const float* g1      = (const float*)d_in[5];
    const float* be1     = (const float*)d_in[6];
    const float* m1      = (const float*)d_in[7];
    const float* v1      = (const float*)d_in[8];
    const float* Wg      = (const float*)d_in[9];
    const float* att_src = (const float*)d_in[10];
    const float* att_dst = (const float*)d_in[11];
    const float* bg      = (const float*)d_in[12];
    const float* g2      = (const float*)d_in[13];
    const float* be2     = (const float*)d_in[14];
    const float* m2      = (const float*)d_in[15];
    const float* v2      = (const float*)d_in[16];
    const float* W3l     = (const float*)d_in[17];
    const float* W3r     = (const float*)d_in[18];
    const float* b3      = (const float*)d_in[19];
    const float* g3      = (const float*)d_in[20];
    const float* be3     = (const float*)d_in[21];
    const float* m3      = (const float*)d_in[22];
    const float* v3      = (const float*)d_in[23];
    const float* Wskip   = (const float*)d_in[24];
    const float* bskip   = (const float*)d_in[25];
    const float* Wc1     = (const float*)d_in[26];
    const float* bc1     = (const float*)d_in[27];
    const float* Wc2     = (const float*)d_in[28];
    const float* bc2     = (const float*)d_in[29];
    float* out = (float*)d_out;

    const int TPB = 256;
    k_count<<<(E_EDGES + TPB - 1) / TPB, TPB>>>(ei);
    k_scan1<<<NB_SCAN, SCAN_B>>>();
    k_scan23<<<NB_SCAN, 256>>>();
    k_scatter<<<(E_EDGES + TPB - 1) / TPB, TPB>>>(ei);
    k_sage1_csr<<<(N_NODES + 7) / 8, TPB>>>(x);
    k_sage1_gemm<<<(N_NODES * H_F + TPB - 1) / TPB, TPB>>>(x, W1l, W1r, b1, g1, be1, m1, v1);
    k_gat_gemm<<<N_NODES / 32, TPB>>>(Wg, att_src, att_dst);
    k_gat_csr<<<(N_NODES + 7) / 8, TPB>>>(bg, g2, be2, m2, v2);
    k_sage3_csr<<<(N_NODES + 7) / 8, TPB>>>();
    k_sage3_cls<<<(N_NODES + 7) / 8, TPB>>>(x, W3l, W3r, b3, g3, be3, m3, v3, Wskip, bskip,
                                            Wc1, bc1, Wc2, bc2, out);
}